// round 13
// baseline (speedup 1.0000x reference)
#include <cuda_runtime.h>
#include <cuda_bf16.h>
#include <math.h>
#include <stdint.h>

// Problem constants
#define BATCH 64
#define CDIM  768
#define TWOC  1536
#define NTOK  1025
#define HW    1024
#define RREG  64
#define SREG  16
#define NHEAD 12
#define HD    64
#define TOPKN 32

#define NTOT   (BATCH * HW)       // 65536 merged N
#define NCHUNK 24                 // 768 / 32
#define STAGE_K 32768             // K-GEMM: 4 tiles x 8KB
#define SMEM_K  (3 * STAGE_K)     // 96KB
#define NSEL   (TOPKN * SREG)     // 512 selected positions / batch
#define BSPLIT 4                  // batch-slices for weight-stationary proj

// ---------------- scratch ----------------
static __device__ float g_k [(size_t)BATCH * CDIM * HW];      // K full, fp32
static __device__ float g_q [BATCH * CDIM];
static __device__ float g_kr[(size_t)BATCH * CDIM * RREG];
static __device__ int   g_sel[BATCH * TOPKN];
static __device__ int   g_nidx[BATCH * NSEL];
static __device__ float g_p [(size_t)BATCH * NSEL * 16];      // p[b][k][16pad(h)]
static __device__ float g_y [BATCH * NHEAD * CDIM];           // y[b][h][768]
static __device__ float g_o [BATCH * CDIM];
static __device__ __align__(128) __nv_bfloat16 g_Ahi[CDIM * CDIM];          // Wk hi
static __device__ __align__(128) __nv_bfloat16 g_Alo[CDIM * CDIM];          // Wk lo
static __device__ __align__(128) __nv_bfloat16 g_Bthi[(size_t)NTOT * CDIM];
static __device__ __align__(128) __nv_bfloat16 g_Btlo[(size_t)NTOT * CDIM];

// ---------------- PTX helpers ----------------
__device__ __forceinline__ uint32_t smem_u32(const void* p) {
    uint32_t a;
    asm("{ .reg .u64 t; cvta.to.shared.u64 t, %1; cvt.u32.u64 %0, t; }" : "=r"(a) : "l"(p));
    return a;
}
__device__ __forceinline__ void cp16(uint32_t dst, const void* src) {
    asm volatile("cp.async.cg.shared.global [%0], [%1], 16;" :: "r"(dst), "l"(src));
}
__device__ __forceinline__ void cp_commit() { asm volatile("cp.async.commit_group;"); }
__device__ __forceinline__ void cp_wait1()  { asm volatile("cp.async.wait_group 1;"); }
__device__ __forceinline__ void cp_wait0()  { asm volatile("cp.async.wait_group 0;"); }
__device__ __forceinline__ void ldsm4(uint32_t* r, uint32_t a) {
    asm volatile("ldmatrix.sync.aligned.m8n8.x4.shared.b16 {%0,%1,%2,%3}, [%4];"
        : "=r"(r[0]), "=r"(r[1]), "=r"(r[2]), "=r"(r[3]) : "r"(a));
}
__device__ __forceinline__ void mma_bf16(float* d, const uint32_t* a, const uint32_t* b) {
    asm volatile("mma.sync.aligned.m16n8k16.row.col.f32.bf16.bf16.f32 "
        "{%0,%1,%2,%3}, {%4,%5,%6,%7}, {%8,%9}, {%0,%1,%2,%3};"
        : "+f"(d[0]), "+f"(d[1]), "+f"(d[2]), "+f"(d[3])
        : "r"(a[0]), "r"(a[1]), "r"(a[2]), "r"(a[3]), "r"(b[0]), "r"(b[1]));
}

// ---------------- K0a: split Wk -> bf16 hi/lo ----------------
__global__ void k_convA(const float* __restrict__ Wkv) {
    int i = blockIdx.x * 256 + threadIdx.x;
    if (i < CDIM * CDIM) {
        float wk = Wkv[i];
        __nv_bfloat16 h = __float2bfloat16(wk);
        g_Ahi[i] = h;
        g_Alo[i] = __float2bfloat16(wk - __bfloat162float(h));
    }
}

// ---------------- K0b: transpose x_spa -> Bt[n,k] bf16 hi/lo ---------------
__global__ void k_convB(const float* __restrict__ x) {
    __shared__ float t[32][33];
    int b  = blockIdx.z;
    int n0 = blockIdx.x * 32;
    int k0 = blockIdx.y * 32;
    const float* src = x + (size_t)b * NTOK * CDIM + CDIM;
    int tx = threadIdx.x, ty = threadIdx.y;
    #pragma unroll
    for (int i = ty; i < 32; i += 8)
        t[i][tx] = src[(size_t)(k0 + i) * HW + n0 + tx];
    __syncthreads();
    #pragma unroll
    for (int i = ty; i < 32; i += 8) {
        float w = t[tx][i];
        __nv_bfloat16 h = __float2bfloat16(w);
        size_t idx = ((size_t)b * HW + n0 + i) * CDIM + k0 + tx;
        g_Bthi[idx] = h;
        g_Btlo[idx] = __float2bfloat16(w - __bfloat162float(h));
    }
}

// ---------------- K1: q projection (weight-stationary) ----------------
__global__ __launch_bounds__(256) void k_qproj(const float* __restrict__ x,
                                               const float* __restrict__ Wq,
                                               const float* __restrict__ bq) {
    __shared__ float wsh[8 * CDIM];
    int tid = threadIdx.x;
    int j0 = blockIdx.x * 8;
    int b0 = blockIdx.y * (BATCH / BSPLIT);
    for (int i = tid; i < 8 * CDIM; i += 256) wsh[i] = Wq[(size_t)j0 * CDIM + i];
    __syncthreads();
    int w = tid >> 5, lane = tid & 31;
    const float* wr = &wsh[w * CDIM];
    float bias = bq[j0 + w];
    for (int b = b0; b < b0 + BATCH / BSPLIT; b++) {
        const float* xb = x + (size_t)b * NTOK * CDIM;
        float s = 0.f;
        #pragma unroll
        for (int c = lane; c < CDIM; c += 32) s += xb[c] * wr[c];
        #pragma unroll
        for (int off = 16; off; off >>= 1) s += __shfl_down_sync(0xffffffffu, s, off);
        if (lane == 0) g_q[b * CDIM + j0 + w] = s + bias;
    }
}

// ---------------- K2: K-GEMM, 3-term split bf16 ----------------
__global__ void __launch_bounds__(256, 2) k_gemm_k(const float* __restrict__ bkv) {
    extern __shared__ __align__(1024) char smem[];
    uint32_t sb = smem_u32(smem);
    int tid = threadIdx.x;
    int m0 = blockIdx.x * 128;            // 6 m-tiles (fast -> B reuse)
    int n0 = blockIdx.y * 128;            // 512 n-tiles

    auto load_stage = [&](uint32_t st, int kc) {
        #pragma unroll
        for (int rep = 0; rep < 2; rep++) {
            int q    = tid + rep * 256;
            int row  = q >> 2, quad = q & 3;
            uint32_t doff = row * 64 + ((quad ^ ((row >> 1) & 3)) << 4);
            size_t aoff = (size_t)(m0 + row) * CDIM + kc + quad * 8;
            size_t boff = (size_t)(n0 + row) * CDIM + kc + quad * 8;
            cp16(st +         doff, g_Ahi  + aoff);
            cp16(st +  8192 + doff, g_Alo  + aoff);
            cp16(st + 16384 + doff, g_Bthi + boff);
            cp16(st + 24576 + doff, g_Btlo + boff);
        }
        cp_commit();
    };

    load_stage(sb, 0);
    load_stage(sb + STAGE_K, 32);

    int lane = tid & 31, wid = tid >> 5;
    int wm = wid >> 2, wn = wid & 3;
    uint32_t a_base = (uint32_t)((wm * 64 + (lane & 15)) * 64);
    uint32_t swa    = ((lane & 15) >> 1) & 3;
    uint32_t akh    = lane >> 4;
    uint32_t b_row  = (uint32_t)(wn * 32 + ((lane >> 4) << 3) + (lane & 7));
    uint32_t b_base = b_row * 64;
    uint32_t swb    = ((((lane >> 4) << 3) + (lane & 7)) >> 1) & 3;
    uint32_t bkh    = (lane >> 3) & 1;

    float acc[4][4][4] = {};

    for (int c = 0; c < NCHUNK; c++) {
        if (c == NCHUNK - 1) cp_wait0(); else cp_wait1();
        __syncthreads();
        if (c + 2 < NCHUNK) load_stage(sb + ((c + 2) % 3) * STAGE_K, (c + 2) * 32);
        uint32_t st = sb + (c % 3) * STAGE_K;
        #pragma unroll
        for (int ks = 0; ks < 2; ks++) {
            uint32_t qk = ks * 2;
            uint32_t aoff = a_base + (((qk + akh) ^ swa) << 4);
            uint32_t boff = b_base + (((qk + bkh) ^ swb) << 4);
            uint32_t ah[4][4], al[4][4], bb[4][2];
            ldsm4(&bb[0][0], st + 16384 + boff);
            ldsm4(&bb[2][0], st + 16384 + boff + 1024);
            #pragma unroll
            for (int mt = 0; mt < 4; mt++) ldsm4(ah[mt], st + mt * 1024 + aoff);
            #pragma unroll
            for (int mt = 0; mt < 4; mt++)
                #pragma unroll
                for (int nt = 0; nt < 4; nt++) mma_bf16(acc[mt][nt], ah[mt], bb[nt]);
            #pragma unroll
            for (int mt = 0; mt < 4; mt++) ldsm4(al[mt], st + 8192 + mt * 1024 + aoff);
            #pragma unroll
            for (int mt = 0; mt < 4; mt++)
                #pragma unroll
                for (int nt = 0; nt < 4; nt++) mma_bf16(acc[mt][nt], al[mt], bb[nt]);
            ldsm4(&bb[0][0], st + 24576 + boff);
            ldsm4(&bb[2][0], st + 24576 + boff + 1024);
            #pragma unroll
            for (int mt = 0; mt < 4; mt++)
                #pragma unroll
                for (int nt = 0; nt < 4; nt++) mma_bf16(acc[mt][nt], ah[mt], bb[nt]);
        }
    }

    int b    = n0 >> 10;
    int pos0 = (n0 & 1023) + wn * 32;
    #pragma unroll
    for (int mt = 0; mt < 4; mt++) {
        int row = m0 + wm * 64 + mt * 16 + (lane >> 2);
        float bias0 = bkv[row], bias8 = bkv[row + 8];
        float* base0 = &g_k[((size_t)b * CDIM + row) * HW + pos0];
        float* base8 = base0 + (size_t)8 * HW;
        #pragma unroll
        for (int nt = 0; nt < 4; nt++) {
            int col = nt * 8 + (lane & 3) * 2;
            *(float2*)&base0[col] = make_float2(acc[mt][nt][0] + bias0, acc[mt][nt][1] + bias0);
            *(float2*)&base8[col] = make_float2(acc[mt][nt][2] + bias8, acc[mt][nt][3] + bias8);
        }
    }
}

// ---------------- K3: region max-pool (on K) ----------------
__global__ void k_pool() {
    int b   = blockIdx.x;
    int lin = blockIdx.y * 256 + threadIdx.x;
    int c = lin >> 6, r = lin & 63;
    int h0 = (r >> 3) * 4, w0 = (r & 7) * 4;
    const float* base = &g_k[((size_t)b * CDIM + c) * HW + h0 * 32 + w0];
    float m = -1e30f;
    #pragma unroll
    for (int dh = 0; dh < 4; dh++) {
        float4 v = *(const float4*)&base[dh * 32];
        m = fmaxf(m, fmaxf(fmaxf(v.x, v.y), fmaxf(v.z, v.w)));
    }
    g_kr[((size_t)b * CDIM + c) * RREG + r] = m;
}

// ---------------- K4: routing + top-32 + selected index build --------------
__global__ void k_route() {
    int b = blockIdx.x, tid = threadIdx.x;
    __shared__ float qs[CDIM];
    __shared__ float part[256];
    __shared__ float a[RREG];
    __shared__ int sel_s[TOPKN];
    for (int c = tid; c < CDIM; c += 256) qs[c] = g_q[b * CDIM + c];
    __syncthreads();
    int r = tid & 63, seg = tid >> 6;
    float s = 0.f;
    int c0 = seg * 192;
    for (int c = c0; c < c0 + 192; c++)
        s += qs[c] * g_kr[((size_t)b * CDIM + c) * RREG + r];
    part[tid] = s;
    __syncthreads();
    if (tid < RREG) a[tid] = part[tid] + part[tid + 64] + part[tid + 128] + part[tid + 192];
    __syncthreads();
    if (tid < RREG) {
        float my = a[tid];
        int rank = 0;
        #pragma unroll 8
        for (int r2 = 0; r2 < RREG; r2++) {
            float v = a[r2];
            rank += (v > my) || (v == my && r2 < tid);
        }
        if (rank < TOPKN) { sel_s[rank] = tid; g_sel[b * TOPKN + rank] = tid; }
    }
    __syncthreads();
    for (int j = tid; j < NSEL; j += 256) {
        int rank = j >> 4, ss = j & 15;
        int reg = sel_s[rank];
        int n = ((reg >> 3) * 4 + (ss >> 2)) * 32 + (reg & 7) * 4 + (ss & 3);
        g_nidx[b * NSEL + j] = b * HW + n;
    }
}

// ---------------- K5: logits + softmax -> normalized p ---------------------
__global__ __launch_bounds__(128) void k_attn_p() {
    int b = blockIdx.x, h = blockIdx.y;
    int tid = threadIdx.x, w = tid >> 5, lane = tid & 31;
    __shared__ float qsh[HD];
    __shared__ float kt[HD * 17];
    __shared__ float lg[NSEL];
    __shared__ float red[4];

    const float SCALE = 0.036084391824351615f;   // 768^-0.5
    int ch0 = h * HD;
    if (tid < HD) qsh[tid] = g_q[b * CDIM + ch0 + tid];
    __syncthreads();

    size_t kb = (size_t)b * CDIM * HW;
    int d  = tid >> 1;
    int p0 = (tid & 1) * 2;

    for (int i = 0; i < TOPKN; i++) {
        int reg = g_sel[b * TOPKN + i];
        int pbase = ((reg >> 3) * 4) * 32 + (reg & 7) * 4;
        {
            const float* sk = &g_k[kb + (size_t)(ch0 + d) * HW + pbase];
            float4 v0 = *(const float4*)&sk[p0 * 32];
            float4 v1 = *(const float4*)&sk[(p0 + 1) * 32];
            float* dk = &kt[d * 17 + p0 * 4];
            dk[0] = v0.x; dk[1] = v0.y; dk[2] = v0.z; dk[3] = v0.w;
            dk[4] = v1.x; dk[5] = v1.y; dk[6] = v1.z; dk[7] = v1.w;
        }
        __syncthreads();
        if (tid < SREG) {
            float s = 0.f;
            #pragma unroll 16
            for (int dd = 0; dd < HD; dd++) s += qsh[dd] * kt[dd * 17 + tid];
            lg[i * SREG + tid] = s * SCALE;
        }
        __syncthreads();
    }
    // block softmax over 512
    float v0 = lg[tid], v1 = lg[tid + 128], v2 = lg[tid + 256], v3 = lg[tid + 384];
    float mx = fmaxf(fmaxf(v0, v1), fmaxf(v2, v3));
    #pragma unroll
    for (int off = 16; off; off >>= 1) mx = fmaxf(mx, __shfl_xor_sync(0xffffffffu, mx, off));
    if (lane == 0) red[w] = mx;
    __syncthreads();
    float M = fmaxf(fmaxf(red[0], red[1]), fmaxf(red[2], red[3]));
    float e0 = expf(v0 - M), e1 = expf(v1 - M), e2 = expf(v2 - M), e3 = expf(v3 - M);
    float su = e0 + e1 + e2 + e3;
    #pragma unroll
    for (int off = 16; off; off >>= 1) su += __shfl_xor_sync(0xffffffffu, su, off);
    __syncthreads();
    if (lane == 0) red[w] = su;
    __syncthreads();
    float L = red[0] + red[1] + red[2] + red[3];
    float inv = 1.f / L;
    size_t pb = (size_t)b * NSEL * 16 + h;
    g_p[pb + (size_t)(tid      ) * 16] = e0 * inv;
    g_p[pb + (size_t)(tid + 128) * 16] = e1 * inv;
    g_p[pb + (size_t)(tid + 256) * 16] = e2 * inv;
    g_p[pb + (size_t)(tid + 384) * 16] = e3 * inv;
}

// ---------------- K6: y[b][h] = sum_k p[h][k] * x[:, n_k] ------------------
__global__ __launch_bounds__(256) void k_yred() {
    __shared__ float ps[NSEL * 16];   // 32KB
    __shared__ int nid[NSEL];
    int b = blockIdx.x;
    int c = blockIdx.y * 256 + threadIdx.x;
    int tid = threadIdx.x;
    for (int i = tid; i < NSEL * 16; i += 256) ps[i] = g_p[(size_t)b * NSEL * 16 + i];
    for (int i = tid; i < NSEL; i += 256) nid[i] = g_nidx[b * NSEL + i];
    __syncthreads();

    float acc[NHEAD] = {};
    #pragma unroll 4
    for (int k = 0; k < NSEL; k++) {
        size_t row = (size_t)nid[k] * CDIM + c;
        float xv = __bfloat162float(g_Bthi[row]) + __bfloat162float(g_Btlo[row]);
        float4 pA = *(const float4*)&ps[k * 16];
        float4 pB = *(const float4*)&ps[k * 16 + 4];
        float4 pC = *(const float4*)&ps[k * 16 + 8];
        acc[0]  += pA.x * xv; acc[1]  += pA.y * xv; acc[2]  += pA.z * xv; acc[3]  += pA.w * xv;
        acc[4]  += pB.x * xv; acc[5]  += pB.y * xv; acc[6]  += pB.z * xv; acc[7]  += pB.w * xv;
        acc[8]  += pC.x * xv; acc[9]  += pC.y * xv; acc[10] += pC.z * xv; acc[11] += pC.w * xv;
    }
    #pragma unroll
    for (int h = 0; h < NHEAD; h++)
        g_y[((size_t)b * NHEAD + h) * CDIM + c] = acc[h];
}

// ---------------- K7: o = Wv_head . y (weight-stationary) ------------------
__global__ __launch_bounds__(256) void k_vproj(const float* __restrict__ Wkv,
                                               const float* __restrict__ bkv) {
    __shared__ float wsh[8 * CDIM];
    int tid = threadIdx.x;
    int j0 = blockIdx.x * 8;
    int b0 = blockIdx.y * (BATCH / BSPLIT);
    int h  = j0 >> 6;   // 8 | 64, so all 8 j share one head
    for (int i = tid; i < 8 * CDIM; i += 256)
        wsh[i] = Wkv[(size_t)(CDIM + j0) * CDIM + i];
    __syncthreads();
    int w = tid >> 5, lane = tid & 31;
    const float* wr = &wsh[w * CDIM];
    float bias = bkv[CDIM + j0 + w];
    for (int b = b0; b < b0 + BATCH / BSPLIT; b++) {
        const float* yb = &g_y[((size_t)b * NHEAD + h) * CDIM];
        float s = 0.f;
        #pragma unroll
        for (int c = lane; c < CDIM; c += 32) s += yb[c] * wr[c];
        #pragma unroll
        for (int off = 16; off; off >>= 1) s += __shfl_down_sync(0xffffffffu, s, off);
        if (lane == 0) g_o[b * CDIM + j0 + w] = s + bias;
    }
}

// ---------------- K8: output projection (weight-stationary) ----------------
__global__ __launch_bounds__(256) void k_outproj(float* __restrict__ out,
                                                 const float* __restrict__ Wo,
                                                 const float* __restrict__ bo,
                                                 int out_cols, int bo_n) {
    __shared__ float wsh[8 * CDIM];
    int tid = threadIdx.x;
    int j0 = blockIdx.x * 8;
    int b0 = blockIdx.y * (BATCH / BSPLIT);
    if (j0 >= out_cols) return;
    for (int i = tid; i < 8 * CDIM; i += 256) {
        if (j0 + (i / CDIM) < out_cols) wsh[i] = Wo[(size_t)j0 * CDIM + i];
    }
    __syncthreads();
    int w = tid >> 5, lane = tid & 31;
    int j = j0 + w;
    if (j >= out_cols) return;
    const float* wr = &wsh[w * CDIM];
    float bias = (j < bo_n) ? bo[j] : 0.f;
    for (int b = b0; b < b0 + BATCH / BSPLIT; b++) {
        const float* ob = &g_o[b * CDIM];
        float s = 0.f;
        #pragma unroll
        for (int c = lane; c < CDIM; c += 32) s += ob[c] * wr[c];
        #pragma unroll
        for (int off = 16; off; off >>= 1) s += __shfl_down_sync(0xffffffffu, s, off);
        if (lane == 0) out[(size_t)b * out_cols + j] = s + bias;
    }
}

// ---------------- host ----------------
extern "C" void kernel_launch(void* const* d_in, const int* in_sizes, int n_in,
                              void* d_out, int out_size) {
    const float* x   = (const float*)d_in[0];
    const float* Wq  = (const float*)d_in[1];
    const float* bq  = (const float*)d_in[2];
    const float* Wkv = (const float*)d_in[3];
    const float* bkv = (const float*)d_in[4];
    const float* Wo  = (const float*)d_in[5];
    const float* bo  = (const float*)d_in[6];
    float* out = (float*)d_out;

    int B = in_sizes[0] / (NTOK * CDIM);
    int out_cols = out_size / B;
    int bo_n = (n_in > 6) ? in_sizes[6] : 0;

    cudaFuncSetAttribute(k_gemm_k, cudaFuncAttributeMaxDynamicSharedMemorySize, SMEM_K);

    k_convA  <<<(CDIM * CDIM + 255) / 256, 256>>>(Wkv);
    k_convB  <<<dim3(HW / 32, CDIM / 32, B), dim3(32, 8)>>>(x);
    k_qproj  <<<dim3(CDIM / 8, BSPLIT), 256>>>(x, Wq, bq);
    k_gemm_k <<<dim3(CDIM / 128, NTOT / 128), 256, SMEM_K>>>(bkv);
    k_pool   <<<dim3(B, (CDIM * RREG) / 256), 256>>>();
    k_route  <<<dim3(B), 256>>>();
    k_attn_p <<<dim3(B, NHEAD), 128>>>();
    k_yred   <<<dim3(B, 3), 256>>>();
    k_vproj  <<<dim3(CDIM / 8, BSPLIT), 256>>>(Wkv, bkv);
    k_outproj<<<dim3((out_cols + 7) / 8, BSPLIT), 256>>>(out, Wo, bo, out_cols, bo_n);
}

// round 14
// speedup vs baseline: 1.3984x; 1.3984x over previous
#include <cuda_runtime.h>
#include <cuda_bf16.h>
#include <math.h>
#include <stdint.h>

// Problem constants
#define BATCH 64
#define CDIM  768
#define TWOC  1536
#define NTOK  1025
#define HW    1024
#define RREG  64
#define SREG  16
#define NHEAD 12
#define HD    64
#define TOPKN 32

#define NTOT   (BATCH * HW)       // 65536 merged N
#define NCHUNK 24                 // 768 / 32
#define STAGE_K 32768             // K-GEMM: 4 tiles x 8KB
#define SMEM_K  (3 * STAGE_K)     // 96KB
#define NSEL   (TOPKN * SREG)     // 512 selected positions / batch
#define BSPLIT 4                  // batch-slices for weight-stationary proj

// ---------------- scratch ----------------
static __device__ float g_k [(size_t)BATCH * CDIM * HW];      // K full, fp32
static __device__ float g_q [BATCH * CDIM];
static __device__ float g_kr[(size_t)BATCH * CDIM * RREG];
static __device__ int   g_sel[BATCH * TOPKN];
static __device__ int   g_nidx[BATCH * NSEL];
static __device__ float g_p [(size_t)BATCH * NSEL * 16];      // p[b][k][16pad(h)]
static __device__ float g_y [BATCH * NHEAD * CDIM];           // y[b][h][768]
static __device__ float g_o [BATCH * CDIM];
static __device__ __align__(128) __nv_bfloat16 g_Ahi[CDIM * CDIM];          // Wk hi
static __device__ __align__(128) __nv_bfloat16 g_Alo[CDIM * CDIM];          // Wk lo
static __device__ __align__(128) __nv_bfloat16 g_Bthi[(size_t)NTOT * CDIM];
static __device__ __align__(128) __nv_bfloat16 g_Btlo[(size_t)NTOT * CDIM];

// ---------------- PTX helpers ----------------
__device__ __forceinline__ uint32_t smem_u32(const void* p) {
    uint32_t a;
    asm("{ .reg .u64 t; cvta.to.shared.u64 t, %1; cvt.u32.u64 %0, t; }" : "=r"(a) : "l"(p));
    return a;
}
__device__ __forceinline__ void cp16(uint32_t dst, const void* src) {
    asm volatile("cp.async.cg.shared.global [%0], [%1], 16;" :: "r"(dst), "l"(src));
}
__device__ __forceinline__ void cp_commit() { asm volatile("cp.async.commit_group;"); }
__device__ __forceinline__ void cp_wait1()  { asm volatile("cp.async.wait_group 1;"); }
__device__ __forceinline__ void cp_wait0()  { asm volatile("cp.async.wait_group 0;"); }
__device__ __forceinline__ void ldsm4(uint32_t* r, uint32_t a) {
    asm volatile("ldmatrix.sync.aligned.m8n8.x4.shared.b16 {%0,%1,%2,%3}, [%4];"
        : "=r"(r[0]), "=r"(r[1]), "=r"(r[2]), "=r"(r[3]) : "r"(a));
}
__device__ __forceinline__ void mma_bf16(float* d, const uint32_t* a, const uint32_t* b) {
    asm volatile("mma.sync.aligned.m16n8k16.row.col.f32.bf16.bf16.f32 "
        "{%0,%1,%2,%3}, {%4,%5,%6,%7}, {%8,%9}, {%0,%1,%2,%3};"
        : "+f"(d[0]), "+f"(d[1]), "+f"(d[2]), "+f"(d[3])
        : "r"(a[0]), "r"(a[1]), "r"(a[2]), "r"(a[3]), "r"(b[0]), "r"(b[1]));
}

// ---------------- K0a: split Wk -> bf16 hi/lo ----------------
__global__ void k_convA(const float* __restrict__ Wkv) {
    int i = blockIdx.x * 256 + threadIdx.x;
    if (i < CDIM * CDIM) {
        float wk = Wkv[i];
        __nv_bfloat16 h = __float2bfloat16(wk);
        g_Ahi[i] = h;
        g_Alo[i] = __float2bfloat16(wk - __bfloat162float(h));
    }
}

// ---------------- K0b: transpose x_spa -> Bt[n,k] bf16 hi/lo ---------------
__global__ void k_convB(const float* __restrict__ x) {
    __shared__ float t[32][33];
    int b  = blockIdx.z;
    int n0 = blockIdx.x * 32;
    int k0 = blockIdx.y * 32;
    const float* src = x + (size_t)b * NTOK * CDIM + CDIM;
    int tx = threadIdx.x, ty = threadIdx.y;
    #pragma unroll
    for (int i = ty; i < 32; i += 8)
        t[i][tx] = src[(size_t)(k0 + i) * HW + n0 + tx];
    __syncthreads();
    #pragma unroll
    for (int i = ty; i < 32; i += 8) {
        float w = t[tx][i];
        __nv_bfloat16 h = __float2bfloat16(w);
        size_t idx = ((size_t)b * HW + n0 + i) * CDIM + k0 + tx;
        g_Bthi[idx] = h;
        g_Btlo[idx] = __float2bfloat16(w - __bfloat162float(h));
    }
}

// ---------------- K1: q projection (weight-stationary) ----------------
__global__ __launch_bounds__(256) void k_qproj(const float* __restrict__ x,
                                               const float* __restrict__ Wq,
                                               const float* __restrict__ bq) {
    __shared__ float wsh[8 * CDIM];
    int tid = threadIdx.x;
    int j0 = blockIdx.x * 8;
    int b0 = blockIdx.y * (BATCH / BSPLIT);
    for (int i = tid; i < 8 * CDIM; i += 256) wsh[i] = Wq[(size_t)j0 * CDIM + i];
    __syncthreads();
    int w = tid >> 5, lane = tid & 31;
    const float* wr = &wsh[w * CDIM];
    float bias = bq[j0 + w];
    for (int b = b0; b < b0 + BATCH / BSPLIT; b++) {
        const float* xb = x + (size_t)b * NTOK * CDIM;
        float s = 0.f;
        #pragma unroll
        for (int c = lane; c < CDIM; c += 32) s += xb[c] * wr[c];
        #pragma unroll
        for (int off = 16; off; off >>= 1) s += __shfl_down_sync(0xffffffffu, s, off);
        if (lane == 0) g_q[b * CDIM + j0 + w] = s + bias;
    }
}

// ---------------- K2: K-GEMM, 3-term split bf16 ----------------
__global__ void __launch_bounds__(256, 2) k_gemm_k(const float* __restrict__ bkv) {
    extern __shared__ __align__(1024) char smem[];
    uint32_t sb = smem_u32(smem);
    int tid = threadIdx.x;
    int m0 = blockIdx.x * 128;            // 6 m-tiles (fast -> B reuse)
    int n0 = blockIdx.y * 128;            // 512 n-tiles

    auto load_stage = [&](uint32_t st, int kc) {
        #pragma unroll
        for (int rep = 0; rep < 2; rep++) {
            int q    = tid + rep * 256;
            int row  = q >> 2, quad = q & 3;
            uint32_t doff = row * 64 + ((quad ^ ((row >> 1) & 3)) << 4);
            size_t aoff = (size_t)(m0 + row) * CDIM + kc + quad * 8;
            size_t boff = (size_t)(n0 + row) * CDIM + kc + quad * 8;
            cp16(st +         doff, g_Ahi  + aoff);
            cp16(st +  8192 + doff, g_Alo  + aoff);
            cp16(st + 16384 + doff, g_Bthi + boff);
            cp16(st + 24576 + doff, g_Btlo + boff);
        }
        cp_commit();
    };

    load_stage(sb, 0);
    load_stage(sb + STAGE_K, 32);

    int lane = tid & 31, wid = tid >> 5;
    int wm = wid >> 2, wn = wid & 3;
    uint32_t a_base = (uint32_t)((wm * 64 + (lane & 15)) * 64);
    uint32_t swa    = ((lane & 15) >> 1) & 3;
    uint32_t akh    = lane >> 4;
    uint32_t b_row  = (uint32_t)(wn * 32 + ((lane >> 4) << 3) + (lane & 7));
    uint32_t b_base = b_row * 64;
    uint32_t swb    = ((((lane >> 4) << 3) + (lane & 7)) >> 1) & 3;
    uint32_t bkh    = (lane >> 3) & 1;

    float acc[4][4][4] = {};

    for (int c = 0; c < NCHUNK; c++) {
        if (c == NCHUNK - 1) cp_wait0(); else cp_wait1();
        __syncthreads();
        if (c + 2 < NCHUNK) load_stage(sb + ((c + 2) % 3) * STAGE_K, (c + 2) * 32);
        uint32_t st = sb + (c % 3) * STAGE_K;
        #pragma unroll
        for (int ks = 0; ks < 2; ks++) {
            uint32_t qk = ks * 2;
            uint32_t aoff = a_base + (((qk + akh) ^ swa) << 4);
            uint32_t boff = b_base + (((qk + bkh) ^ swb) << 4);
            uint32_t ah[4][4], al[4][4], bb[4][2];
            ldsm4(&bb[0][0], st + 16384 + boff);
            ldsm4(&bb[2][0], st + 16384 + boff + 1024);
            #pragma unroll
            for (int mt = 0; mt < 4; mt++) ldsm4(ah[mt], st + mt * 1024 + aoff);
            #pragma unroll
            for (int mt = 0; mt < 4; mt++)
                #pragma unroll
                for (int nt = 0; nt < 4; nt++) mma_bf16(acc[mt][nt], ah[mt], bb[nt]);
            #pragma unroll
            for (int mt = 0; mt < 4; mt++) ldsm4(al[mt], st + 8192 + mt * 1024 + aoff);
            #pragma unroll
            for (int mt = 0; mt < 4; mt++)
                #pragma unroll
                for (int nt = 0; nt < 4; nt++) mma_bf16(acc[mt][nt], al[mt], bb[nt]);
            ldsm4(&bb[0][0], st + 24576 + boff);
            ldsm4(&bb[2][0], st + 24576 + boff + 1024);
            #pragma unroll
            for (int mt = 0; mt < 4; mt++)
                #pragma unroll
                for (int nt = 0; nt < 4; nt++) mma_bf16(acc[mt][nt], ah[mt], bb[nt]);
        }
    }

    int b    = n0 >> 10;
    int pos0 = (n0 & 1023) + wn * 32;
    #pragma unroll
    for (int mt = 0; mt < 4; mt++) {
        int row = m0 + wm * 64 + mt * 16 + (lane >> 2);
        float bias0 = bkv[row], bias8 = bkv[row + 8];
        float* base0 = &g_k[((size_t)b * CDIM + row) * HW + pos0];
        float* base8 = base0 + (size_t)8 * HW;
        #pragma unroll
        for (int nt = 0; nt < 4; nt++) {
            int col = nt * 8 + (lane & 3) * 2;
            *(float2*)&base0[col] = make_float2(acc[mt][nt][0] + bias0, acc[mt][nt][1] + bias0);
            *(float2*)&base8[col] = make_float2(acc[mt][nt][2] + bias8, acc[mt][nt][3] + bias8);
        }
    }
}

// ---------------- K3: region max-pool (on K) ----------------
__global__ void k_pool() {
    int b   = blockIdx.x;
    int lin = blockIdx.y * 256 + threadIdx.x;
    int c = lin >> 6, r = lin & 63;
    int h0 = (r >> 3) * 4, w0 = (r & 7) * 4;
    const float* base = &g_k[((size_t)b * CDIM + c) * HW + h0 * 32 + w0];
    float m = -1e30f;
    #pragma unroll
    for (int dh = 0; dh < 4; dh++) {
        float4 v = *(const float4*)&base[dh * 32];
        m = fmaxf(m, fmaxf(fmaxf(v.x, v.y), fmaxf(v.z, v.w)));
    }
    g_kr[((size_t)b * CDIM + c) * RREG + r] = m;
}

// ---------------- K4: routing + top-32 + selected index build --------------
__global__ void k_route() {
    int b = blockIdx.x, tid = threadIdx.x;
    __shared__ float qs[CDIM];
    __shared__ float part[256];
    __shared__ float a[RREG];
    __shared__ int sel_s[TOPKN];
    for (int c = tid; c < CDIM; c += 256) qs[c] = g_q[b * CDIM + c];
    __syncthreads();
    int r = tid & 63, seg = tid >> 6;
    float s = 0.f;
    int c0 = seg * 192;
    for (int c = c0; c < c0 + 192; c++)
        s += qs[c] * g_kr[((size_t)b * CDIM + c) * RREG + r];
    part[tid] = s;
    __syncthreads();
    if (tid < RREG) a[tid] = part[tid] + part[tid + 64] + part[tid + 128] + part[tid + 192];
    __syncthreads();
    if (tid < RREG) {
        float my = a[tid];
        int rank = 0;
        #pragma unroll 8
        for (int r2 = 0; r2 < RREG; r2++) {
            float v = a[r2];
            rank += (v > my) || (v == my && r2 < tid);
        }
        if (rank < TOPKN) { sel_s[rank] = tid; g_sel[b * TOPKN + rank] = tid; }
    }
    __syncthreads();
    for (int j = tid; j < NSEL; j += 256) {
        int rank = j >> 4, ss = j & 15;
        int reg = sel_s[rank];
        int n = ((reg >> 3) * 4 + (ss >> 2)) * 32 + (reg & 7) * 4 + (ss & 3);
        g_nidx[b * NSEL + j] = b * HW + n;
    }
}

// ---------------- K5: logits + softmax -> normalized p ---------------------
__global__ __launch_bounds__(128) void k_attn_p() {
    int b = blockIdx.x, h = blockIdx.y;
    int tid = threadIdx.x, w = tid >> 5, lane = tid & 31;
    __shared__ float qsh[HD];
    __shared__ float kt[HD * 17];
    __shared__ float lg[NSEL];
    __shared__ float red[4];

    const float SCALE = 0.036084391824351615f;   // 768^-0.5
    int ch0 = h * HD;
    if (tid < HD) qsh[tid] = g_q[b * CDIM + ch0 + tid];
    __syncthreads();

    size_t kb = (size_t)b * CDIM * HW;
    int d  = tid >> 1;
    int p0 = (tid & 1) * 2;

    for (int i = 0; i < TOPKN; i++) {
        int reg = g_sel[b * TOPKN + i];
        int pbase = ((reg >> 3) * 4) * 32 + (reg & 7) * 4;
        {
            const float* sk = &g_k[kb + (size_t)(ch0 + d) * HW + pbase];
            float4 v0 = *(const float4*)&sk[p0 * 32];
            float4 v1 = *(const float4*)&sk[(p0 + 1) * 32];
            float* dk = &kt[d * 17 + p0 * 4];
            dk[0] = v0.x; dk[1] = v0.y; dk[2] = v0.z; dk[3] = v0.w;
            dk[4] = v1.x; dk[5] = v1.y; dk[6] = v1.z; dk[7] = v1.w;
        }
        __syncthreads();
        if (tid < SREG) {
            float s = 0.f;
            #pragma unroll 16
            for (int dd = 0; dd < HD; dd++) s += qsh[dd] * kt[dd * 17 + tid];
            lg[i * SREG + tid] = s * SCALE;
        }
        __syncthreads();
    }
    // block softmax over 512
    float v0 = lg[tid], v1 = lg[tid + 128], v2 = lg[tid + 256], v3 = lg[tid + 384];
    float mx = fmaxf(fmaxf(v0, v1), fmaxf(v2, v3));
    #pragma unroll
    for (int off = 16; off; off >>= 1) mx = fmaxf(mx, __shfl_xor_sync(0xffffffffu, mx, off));
    if (lane == 0) red[w] = mx;
    __syncthreads();
    float M = fmaxf(fmaxf(red[0], red[1]), fmaxf(red[2], red[3]));
    float e0 = expf(v0 - M), e1 = expf(v1 - M), e2 = expf(v2 - M), e3 = expf(v3 - M);
    float su = e0 + e1 + e2 + e3;
    #pragma unroll
    for (int off = 16; off; off >>= 1) su += __shfl_xor_sync(0xffffffffu, su, off);
    __syncthreads();
    if (lane == 0) red[w] = su;
    __syncthreads();
    float L = red[0] + red[1] + red[2] + red[3];
    float inv = 1.f / L;
    size_t pb = (size_t)b * NSEL * 16 + h;
    g_p[pb + (size_t)(tid      ) * 16] = e0 * inv;
    g_p[pb + (size_t)(tid + 128) * 16] = e1 * inv;
    g_p[pb + (size_t)(tid + 256) * 16] = e2 * inv;
    g_p[pb + (size_t)(tid + 384) * 16] = e3 * inv;
}

// ---------------- K6: y[b][h] = sum_k p[h][k] * x[:, n_k] ------------------
__global__ __launch_bounds__(256) void k_yred() {
    __shared__ float ps[NSEL * 16];   // 32KB
    __shared__ int nid[NSEL];
    int b = blockIdx.x;
    int c = blockIdx.y * 256 + threadIdx.x;
    int tid = threadIdx.x;
    for (int i = tid; i < NSEL * 16; i += 256) ps[i] = g_p[(size_t)b * NSEL * 16 + i];
    for (int i = tid; i < NSEL; i += 256) nid[i] = g_nidx[b * NSEL + i];
    __syncthreads();

    float acc[NHEAD] = {};
    #pragma unroll 4
    for (int k = 0; k < NSEL; k++) {
        size_t row = (size_t)nid[k] * CDIM + c;
        float xv = __bfloat162float(g_Bthi[row]) + __bfloat162float(g_Btlo[row]);
        float4 pA = *(const float4*)&ps[k * 16];
        float4 pB = *(const float4*)&ps[k * 16 + 4];
        float4 pC = *(const float4*)&ps[k * 16 + 8];
        acc[0]  += pA.x * xv; acc[1]  += pA.y * xv; acc[2]  += pA.z * xv; acc[3]  += pA.w * xv;
        acc[4]  += pB.x * xv; acc[5]  += pB.y * xv; acc[6]  += pB.z * xv; acc[7]  += pB.w * xv;
        acc[8]  += pC.x * xv; acc[9]  += pC.y * xv; acc[10] += pC.z * xv; acc[11] += pC.w * xv;
    }
    #pragma unroll
    for (int h = 0; h < NHEAD; h++)
        g_y[((size_t)b * NHEAD + h) * CDIM + c] = acc[h];
}

// ---------------- K7: o = Wv_head . y (weight-stationary) ------------------
__global__ __launch_bounds__(256) void k_vproj(const float* __restrict__ Wkv,
                                               const float* __restrict__ bkv) {
    __shared__ float wsh[8 * CDIM];
    int tid = threadIdx.x;
    int j0 = blockIdx.x * 8;
    int b0 = blockIdx.y * (BATCH / BSPLIT);
    int h  = j0 >> 6;   // 8 | 64, so all 8 j share one head
    for (int i = tid; i < 8 * CDIM; i += 256)
        wsh[i] = Wkv[(size_t)(CDIM + j0) * CDIM + i];
    __syncthreads();
    int w = tid >> 5, lane = tid & 31;
    const float* wr = &wsh[w * CDIM];
    float bias = bkv[CDIM + j0 + w];
    for (int b = b0; b < b0 + BATCH / BSPLIT; b++) {
        const float* yb = &g_y[((size_t)b * NHEAD + h) * CDIM];
        float s = 0.f;
        #pragma unroll
        for (int c = lane; c < CDIM; c += 32) s += yb[c] * wr[c];
        #pragma unroll
        for (int off = 16; off; off >>= 1) s += __shfl_down_sync(0xffffffffu, s, off);
        if (lane == 0) g_o[b * CDIM + j0 + w] = s + bias;
    }
}

// ---------------- K8: output projection (weight-stationary) ----------------
__global__ __launch_bounds__(256) void k_outproj(float* __restrict__ out,
                                                 const float* __restrict__ Wo,
                                                 const float* __restrict__ bo,
                                                 int out_cols, int bo_n) {
    __shared__ float wsh[8 * CDIM];
    int tid = threadIdx.x;
    int j0 = blockIdx.x * 8;
    int b0 = blockIdx.y * (BATCH / BSPLIT);
    if (j0 >= out_cols) return;
    for (int i = tid; i < 8 * CDIM; i += 256) {
        if (j0 + (i / CDIM) < out_cols) wsh[i] = Wo[(size_t)j0 * CDIM + i];
    }
    __syncthreads();
    int w = tid >> 5, lane = tid & 31;
    int j = j0 + w;
    if (j >= out_cols) return;
    const float* wr = &wsh[w * CDIM];
    float bias = (j < bo_n) ? bo[j] : 0.f;
    for (int b = b0; b < b0 + BATCH / BSPLIT; b++) {
        const float* ob = &g_o[b * CDIM];
        float s = 0.f;
        #pragma unroll
        for (int c = lane; c < CDIM; c += 32) s += ob[c] * wr[c];
        #pragma unroll
        for (int off = 16; off; off >>= 1) s += __shfl_down_sync(0xffffffffu, s, off);
        if (lane == 0) out[(size_t)b * out_cols + j] = s + bias;
    }
}

// ---------------- host ----------------
extern "C" void kernel_launch(void* const* d_in, const int* in_sizes, int n_in,
                              void* d_out, int out_size) {
    const float* x   = (const float*)d_in[0];
    const float* Wq  = (const float*)d_in[1];
    const float* bq  = (const float*)d_in[2];
    const float* Wkv = (const float*)d_in[3];
    const float* bkv = (const float*)d_in[4];
    const float* Wo  = (const float*)d_in[5];
    const float* bo  = (const float*)d_in[6];
    float* out = (float*)d_out;

    int B = in_sizes[0] / (NTOK * CDIM);
    int out_cols = out_size / B;
    int bo_n = (n_in > 6) ? in_sizes[6] : 0;

    cudaFuncSetAttribute(k_gemm_k, cudaFuncAttributeMaxDynamicSharedMemorySize, SMEM_K);

    k_convA  <<<(CDIM * CDIM + 255) / 256, 256>>>(Wkv);
    k_convB  <<<dim3(HW / 32, CDIM / 32, B), dim3(32, 8)>>>(x);
    k_qproj  <<<dim3(CDIM / 8, BSPLIT), 256>>>(x, Wq, bq);
    k_gemm_k <<<dim3(CDIM / 128, NTOT / 128), 256, SMEM_K>>>(bkv);
    k_pool   <<<dim3(B, (CDIM * RREG) / 256), 256>>>();
    k_route  <<<dim3(B), 256>>>();
    k_attn_p <<<dim3(B, NHEAD), 128>>>();
    k_yred   <<<dim3(B, 3), 256>>>();
    k_vproj  <<<dim3(CDIM / 8, BSPLIT), 256>>>(Wkv, bkv);
    k_outproj<<<dim3((out_cols + 7) / 8, BSPLIT), 256>>>(out, Wo, bo, out_cols, bo_n);
}

// round 15
// speedup vs baseline: 1.4649x; 1.0476x over previous
#include <cuda_runtime.h>
#include <cuda_bf16.h>
#include <math.h>
#include <stdint.h>

// Problem constants
#define BATCH 64
#define CDIM  768
#define TWOC  1536
#define NTOK  1025
#define HW    1024
#define RREG  64
#define SREG  16
#define NHEAD 12
#define HD    64
#define TOPKN 32

#define NTOT   (BATCH * HW)       // 65536 merged N
#define NCHUNK 24                 // 768 / 32
#define STAGE_K 32768             // K-GEMM: 4 tiles x 8KB
#define SMEM_K  (3 * STAGE_K)     // 96KB
#define NSEL   (TOPKN * SREG)     // 512 selected positions / batch
#define BSPLIT 4                  // batch-slices for weight-stationary proj
#define YSPLIT 4                  // position-splits for yred
#define YP_PLANE (BATCH * NHEAD * CDIM)

// ---------------- scratch ----------------
static __device__ float g_k [(size_t)BATCH * CDIM * HW];      // K full, fp32
static __device__ float g_q [BATCH * CDIM];
static __device__ float g_kr[(size_t)BATCH * CDIM * RREG];
static __device__ int   g_sel[BATCH * TOPKN];
static __device__ int   g_nidx[BATCH * NSEL];
static __device__ float g_lgb[(size_t)BATCH * NHEAD * NSEL];  // raw logits
static __device__ float g_p [(size_t)BATCH * NSEL * 16];      // p[b][k][16pad(h)]
static __device__ float g_yp[(size_t)YSPLIT * YP_PLANE];      // y partials
static __device__ float g_y [YP_PLANE];                       // y[b][h][768]
static __device__ float g_o [BATCH * CDIM];
static __device__ __align__(128) __nv_bfloat16 g_Ahi[CDIM * CDIM];          // Wk hi
static __device__ __align__(128) __nv_bfloat16 g_Alo[CDIM * CDIM];          // Wk lo
static __device__ __align__(128) __nv_bfloat16 g_Bthi[(size_t)NTOT * CDIM];
static __device__ __align__(128) __nv_bfloat16 g_Btlo[(size_t)NTOT * CDIM];

// ---------------- PTX helpers ----------------
__device__ __forceinline__ uint32_t smem_u32(const void* p) {
    uint32_t a;
    asm("{ .reg .u64 t; cvta.to.shared.u64 t, %1; cvt.u32.u64 %0, t; }" : "=r"(a) : "l"(p));
    return a;
}
__device__ __forceinline__ void cp16(uint32_t dst, const void* src) {
    asm volatile("cp.async.cg.shared.global [%0], [%1], 16;" :: "r"(dst), "l"(src));
}
__device__ __forceinline__ void cp_commit() { asm volatile("cp.async.commit_group;"); }
__device__ __forceinline__ void cp_wait1()  { asm volatile("cp.async.wait_group 1;"); }
__device__ __forceinline__ void cp_wait0()  { asm volatile("cp.async.wait_group 0;"); }
__device__ __forceinline__ void ldsm4(uint32_t* r, uint32_t a) {
    asm volatile("ldmatrix.sync.aligned.m8n8.x4.shared.b16 {%0,%1,%2,%3}, [%4];"
        : "=r"(r[0]), "=r"(r[1]), "=r"(r[2]), "=r"(r[3]) : "r"(a));
}
__device__ __forceinline__ void mma_bf16(float* d, const uint32_t* a, const uint32_t* b) {
    asm volatile("mma.sync.aligned.m16n8k16.row.col.f32.bf16.bf16.f32 "
        "{%0,%1,%2,%3}, {%4,%5,%6,%7}, {%8,%9}, {%0,%1,%2,%3};"
        : "+f"(d[0]), "+f"(d[1]), "+f"(d[2]), "+f"(d[3])
        : "r"(a[0]), "r"(a[1]), "r"(a[2]), "r"(a[3]), "r"(b[0]), "r"(b[1]));
}

// ---------------- K0a: split Wk -> bf16 hi/lo ----------------
__global__ void k_convA(const float* __restrict__ Wkv) {
    int i = blockIdx.x * 256 + threadIdx.x;
    if (i < CDIM * CDIM) {
        float wk = Wkv[i];
        __nv_bfloat16 h = __float2bfloat16(wk);
        g_Ahi[i] = h;
        g_Alo[i] = __float2bfloat16(wk - __bfloat162float(h));
    }
}

// ---------------- K0b: transpose x_spa -> Bt[n,k] bf16 hi/lo ---------------
__global__ void k_convB(const float* __restrict__ x) {
    __shared__ float t[32][33];
    int b  = blockIdx.z;
    int n0 = blockIdx.x * 32;
    int k0 = blockIdx.y * 32;
    const float* src = x + (size_t)b * NTOK * CDIM + CDIM;
    int tx = threadIdx.x, ty = threadIdx.y;
    #pragma unroll
    for (int i = ty; i < 32; i += 8)
        t[i][tx] = src[(size_t)(k0 + i) * HW + n0 + tx];
    __syncthreads();
    #pragma unroll
    for (int i = ty; i < 32; i += 8) {
        float w = t[tx][i];
        __nv_bfloat16 h = __float2bfloat16(w);
        size_t idx = ((size_t)b * HW + n0 + i) * CDIM + k0 + tx;
        g_Bthi[idx] = h;
        g_Btlo[idx] = __float2bfloat16(w - __bfloat162float(h));
    }
}

// ---------------- K1: q projection (weight-stationary) ----------------
__global__ __launch_bounds__(256) void k_qproj(const float* __restrict__ x,
                                               const float* __restrict__ Wq,
                                               const float* __restrict__ bq) {
    __shared__ float wsh[8 * CDIM];
    int tid = threadIdx.x;
    int j0 = blockIdx.x * 8;
    int b0 = blockIdx.y * (BATCH / BSPLIT);
    for (int i = tid; i < 8 * CDIM; i += 256) wsh[i] = Wq[(size_t)j0 * CDIM + i];
    __syncthreads();
    int w = tid >> 5, lane = tid & 31;
    const float* wr = &wsh[w * CDIM];
    float bias = bq[j0 + w];
    for (int b = b0; b < b0 + BATCH / BSPLIT; b++) {
        const float* xb = x + (size_t)b * NTOK * CDIM;
        float s = 0.f;
        #pragma unroll
        for (int c = lane; c < CDIM; c += 32) s += xb[c] * wr[c];
        #pragma unroll
        for (int off = 16; off; off >>= 1) s += __shfl_down_sync(0xffffffffu, s, off);
        if (lane == 0) g_q[b * CDIM + j0 + w] = s + bias;
    }
}

// ---------------- K2: K-GEMM, 3-term split bf16 ----------------
__global__ void __launch_bounds__(256, 2) k_gemm_k(const float* __restrict__ bkv) {
    extern __shared__ __align__(1024) char smem[];
    uint32_t sb = smem_u32(smem);
    int tid = threadIdx.x;
    int m0 = blockIdx.x * 128;            // 6 m-tiles (fast -> B reuse)
    int n0 = blockIdx.y * 128;            // 512 n-tiles

    auto load_stage = [&](uint32_t st, int kc) {
        #pragma unroll
        for (int rep = 0; rep < 2; rep++) {
            int q    = tid + rep * 256;
            int row  = q >> 2, quad = q & 3;
            uint32_t doff = row * 64 + ((quad ^ ((row >> 1) & 3)) << 4);
            size_t aoff = (size_t)(m0 + row) * CDIM + kc + quad * 8;
            size_t boff = (size_t)(n0 + row) * CDIM + kc + quad * 8;
            cp16(st +         doff, g_Ahi  + aoff);
            cp16(st +  8192 + doff, g_Alo  + aoff);
            cp16(st + 16384 + doff, g_Bthi + boff);
            cp16(st + 24576 + doff, g_Btlo + boff);
        }
        cp_commit();
    };

    load_stage(sb, 0);
    load_stage(sb + STAGE_K, 32);

    int lane = tid & 31, wid = tid >> 5;
    int wm = wid >> 2, wn = wid & 3;
    uint32_t a_base = (uint32_t)((wm * 64 + (lane & 15)) * 64);
    uint32_t swa    = ((lane & 15) >> 1) & 3;
    uint32_t akh    = lane >> 4;
    uint32_t b_row  = (uint32_t)(wn * 32 + ((lane >> 4) << 3) + (lane & 7));
    uint32_t b_base = b_row * 64;
    uint32_t swb    = ((((lane >> 4) << 3) + (lane & 7)) >> 1) & 3;
    uint32_t bkh    = (lane >> 3) & 1;

    float acc[4][4][4] = {};

    for (int c = 0; c < NCHUNK; c++) {
        if (c == NCHUNK - 1) cp_wait0(); else cp_wait1();
        __syncthreads();
        if (c + 2 < NCHUNK) load_stage(sb + ((c + 2) % 3) * STAGE_K, (c + 2) * 32);
        uint32_t st = sb + (c % 3) * STAGE_K;
        #pragma unroll
        for (int ks = 0; ks < 2; ks++) {
            uint32_t qk = ks * 2;
            uint32_t aoff = a_base + (((qk + akh) ^ swa) << 4);
            uint32_t boff = b_base + (((qk + bkh) ^ swb) << 4);
            uint32_t ah[4][4], al[4][4], bb[4][2];
            ldsm4(&bb[0][0], st + 16384 + boff);
            ldsm4(&bb[2][0], st + 16384 + boff + 1024);
            #pragma unroll
            for (int mt = 0; mt < 4; mt++) ldsm4(ah[mt], st + mt * 1024 + aoff);
            #pragma unroll
            for (int mt = 0; mt < 4; mt++)
                #pragma unroll
                for (int nt = 0; nt < 4; nt++) mma_bf16(acc[mt][nt], ah[mt], bb[nt]);
            #pragma unroll
            for (int mt = 0; mt < 4; mt++) ldsm4(al[mt], st + 8192 + mt * 1024 + aoff);
            #pragma unroll
            for (int mt = 0; mt < 4; mt++)
                #pragma unroll
                for (int nt = 0; nt < 4; nt++) mma_bf16(acc[mt][nt], al[mt], bb[nt]);
            ldsm4(&bb[0][0], st + 24576 + boff);
            ldsm4(&bb[2][0], st + 24576 + boff + 1024);
            #pragma unroll
            for (int mt = 0; mt < 4; mt++)
                #pragma unroll
                for (int nt = 0; nt < 4; nt++) mma_bf16(acc[mt][nt], ah[mt], bb[nt]);
        }
    }

    int b    = n0 >> 10;
    int pos0 = (n0 & 1023) + wn * 32;
    #pragma unroll
    for (int mt = 0; mt < 4; mt++) {
        int row = m0 + wm * 64 + mt * 16 + (lane >> 2);
        float bias0 = bkv[row], bias8 = bkv[row + 8];
        float* base0 = &g_k[((size_t)b * CDIM + row) * HW + pos0];
        float* base8 = base0 + (size_t)8 * HW;
        #pragma unroll
        for (int nt = 0; nt < 4; nt++) {
            int col = nt * 8 + (lane & 3) * 2;
            *(float2*)&base0[col] = make_float2(acc[mt][nt][0] + bias0, acc[mt][nt][1] + bias0);
            *(float2*)&base8[col] = make_float2(acc[mt][nt][2] + bias8, acc[mt][nt][3] + bias8);
        }
    }
}

// ---------------- K3: region max-pool (on K) ----------------
__global__ void k_pool() {
    int b   = blockIdx.x;
    int lin = blockIdx.y * 256 + threadIdx.x;
    int c = lin >> 6, r = lin & 63;
    int h0 = (r >> 3) * 4, w0 = (r & 7) * 4;
    const float* base = &g_k[((size_t)b * CDIM + c) * HW + h0 * 32 + w0];
    float m = -1e30f;
    #pragma unroll
    for (int dh = 0; dh < 4; dh++) {
        float4 v = *(const float4*)&base[dh * 32];
        m = fmaxf(m, fmaxf(fmaxf(v.x, v.y), fmaxf(v.z, v.w)));
    }
    g_kr[((size_t)b * CDIM + c) * RREG + r] = m;
}

// ---------------- K4: routing + top-32 + selected index build --------------
__global__ void k_route() {
    int b = blockIdx.x, tid = threadIdx.x;
    __shared__ float qs[CDIM];
    __shared__ float part[256];
    __shared__ float a[RREG];
    __shared__ int sel_s[TOPKN];
    for (int c = tid; c < CDIM; c += 256) qs[c] = g_q[b * CDIM + c];
    __syncthreads();
    int r = tid & 63, seg = tid >> 6;
    float s = 0.f;
    int c0 = seg * 192;
    for (int c = c0; c < c0 + 192; c++)
        s += qs[c] * g_kr[((size_t)b * CDIM + c) * RREG + r];
    part[tid] = s;
    __syncthreads();
    if (tid < RREG) a[tid] = part[tid] + part[tid + 64] + part[tid + 128] + part[tid + 192];
    __syncthreads();
    if (tid < RREG) {
        float my = a[tid];
        int rank = 0;
        #pragma unroll 8
        for (int r2 = 0; r2 < RREG; r2++) {
            float v = a[r2];
            rank += (v > my) || (v == my && r2 < tid);
        }
        if (rank < TOPKN) { sel_s[rank] = tid; g_sel[b * TOPKN + rank] = tid; }
    }
    __syncthreads();
    for (int j = tid; j < NSEL; j += 256) {
        int rank = j >> 4, ss = j & 15;
        int reg = sel_s[rank];
        int n = ((reg >> 3) * 4 + (ss >> 2)) * 32 + (reg & 7) * 4 + (ss & 3);
        g_nidx[b * NSEL + j] = b * HW + n;
    }
}

// ---------------- K5a: logits for 8 regions per block ----------------------
__global__ __launch_bounds__(128) void k_attn_lg() {
    int b = blockIdx.x, h = blockIdx.y, z = blockIdx.z;
    int tid = threadIdx.x;
    __shared__ float qsh[HD];
    __shared__ float kt[HD * 17];

    const float SCALE = 0.036084391824351615f;   // 768^-0.5
    int ch0 = h * HD;
    if (tid < HD) qsh[tid] = g_q[b * CDIM + ch0 + tid];
    __syncthreads();

    size_t kb = (size_t)b * CDIM * HW;
    int d  = tid >> 1;
    int p0 = (tid & 1) * 2;
    size_t lgbase = ((size_t)b * NHEAD + h) * NSEL;

    for (int ii = 0; ii < TOPKN / 4; ii++) {
        int i = z * (TOPKN / 4) + ii;
        int reg = g_sel[b * TOPKN + i];
        int pbase = ((reg >> 3) * 4) * 32 + (reg & 7) * 4;
        {
            const float* sk = &g_k[kb + (size_t)(ch0 + d) * HW + pbase];
            float4 v0 = *(const float4*)&sk[p0 * 32];
            float4 v1 = *(const float4*)&sk[(p0 + 1) * 32];
            float* dk = &kt[d * 17 + p0 * 4];
            dk[0] = v0.x; dk[1] = v0.y; dk[2] = v0.z; dk[3] = v0.w;
            dk[4] = v1.x; dk[5] = v1.y; dk[6] = v1.z; dk[7] = v1.w;
        }
        __syncthreads();
        if (tid < SREG) {
            float s = 0.f;
            #pragma unroll 16
            for (int dd = 0; dd < HD; dd++) s += qsh[dd] * kt[dd * 17 + tid];
            g_lgb[lgbase + i * SREG + tid] = s * SCALE;
        }
        __syncthreads();
    }
}

// ---------------- K5b: softmax over 512 -> normalized p --------------------
__global__ __launch_bounds__(128) void k_attn_sm() {
    int b = blockIdx.x, h = blockIdx.y;
    int tid = threadIdx.x, w = tid >> 5, lane = tid & 31;
    __shared__ float red[4];
    size_t lgbase = ((size_t)b * NHEAD + h) * NSEL;
    float v0 = g_lgb[lgbase + tid], v1 = g_lgb[lgbase + tid + 128];
    float v2 = g_lgb[lgbase + tid + 256], v3 = g_lgb[lgbase + tid + 384];
    float mx = fmaxf(fmaxf(v0, v1), fmaxf(v2, v3));
    #pragma unroll
    for (int off = 16; off; off >>= 1) mx = fmaxf(mx, __shfl_xor_sync(0xffffffffu, mx, off));
    if (lane == 0) red[w] = mx;
    __syncthreads();
    float M = fmaxf(fmaxf(red[0], red[1]), fmaxf(red[2], red[3]));
    float e0 = expf(v0 - M), e1 = expf(v1 - M), e2 = expf(v2 - M), e3 = expf(v3 - M);
    float su = e0 + e1 + e2 + e3;
    #pragma unroll
    for (int off = 16; off; off >>= 1) su += __shfl_xor_sync(0xffffffffu, su, off);
    __syncthreads();
    if (lane == 0) red[w] = su;
    __syncthreads();
    float L = red[0] + red[1] + red[2] + red[3];
    float inv = 1.f / L;
    size_t pb = (size_t)b * NSEL * 16 + h;
    g_p[pb + (size_t)(tid      ) * 16] = e0 * inv;
    g_p[pb + (size_t)(tid + 128) * 16] = e1 * inv;
    g_p[pb + (size_t)(tid + 256) * 16] = e2 * inv;
    g_p[pb + (size_t)(tid + 384) * 16] = e3 * inv;
}

// ---------------- K6: y partials over a 128-position slice -----------------
__global__ __launch_bounds__(256) void k_yred() {
    __shared__ float ps[(NSEL / YSPLIT) * 16];   // 8KB
    __shared__ int nid[NSEL / YSPLIT];
    int b = blockIdx.x;
    int c = blockIdx.y * 256 + threadIdx.x;
    int z = blockIdx.z;
    int k0 = z * (NSEL / YSPLIT);
    int tid = threadIdx.x;
    for (int i = tid; i < (NSEL / YSPLIT) * 16; i += 256)
        ps[i] = g_p[((size_t)b * NSEL + k0) * 16 + i];
    for (int i = tid; i < NSEL / YSPLIT; i += 256)
        nid[i] = g_nidx[b * NSEL + k0 + i];
    __syncthreads();

    float acc[NHEAD] = {};
    #pragma unroll 4
    for (int k = 0; k < NSEL / YSPLIT; k++) {
        size_t row = (size_t)nid[k] * CDIM + c;
        float xv = __bfloat162float(g_Bthi[row]) + __bfloat162float(g_Btlo[row]);
        float4 pA = *(const float4*)&ps[k * 16];
        float4 pB = *(const float4*)&ps[k * 16 + 4];
        float4 pC = *(const float4*)&ps[k * 16 + 8];
        acc[0]  += pA.x * xv; acc[1]  += pA.y * xv; acc[2]  += pA.z * xv; acc[3]  += pA.w * xv;
        acc[4]  += pB.x * xv; acc[5]  += pB.y * xv; acc[6]  += pB.z * xv; acc[7]  += pB.w * xv;
        acc[8]  += pC.x * xv; acc[9]  += pC.y * xv; acc[10] += pC.z * xv; acc[11] += pC.w * xv;
    }
    #pragma unroll
    for (int h = 0; h < NHEAD; h++)
        g_yp[(size_t)z * YP_PLANE + ((size_t)b * NHEAD + h) * CDIM + c] = acc[h];
}

// ---------------- K6b: merge y partials ----------------
__global__ void k_ymerge() {
    int i = blockIdx.x * 256 + threadIdx.x;
    if (i < YP_PLANE)
        g_y[i] = g_yp[i] + g_yp[i + YP_PLANE] + g_yp[i + 2 * YP_PLANE] + g_yp[i + 3 * YP_PLANE];
}

// ---------------- K7: o = Wv_head . y (weight-stationary) ------------------
__global__ __launch_bounds__(256) void k_vproj(const float* __restrict__ Wkv,
                                               const float* __restrict__ bkv) {
    __shared__ float wsh[8 * CDIM];
    int tid = threadIdx.x;
    int j0 = blockIdx.x * 8;
    int b0 = blockIdx.y * (BATCH / BSPLIT);
    int h  = j0 >> 6;   // 8 | 64, so all 8 j share one head
    for (int i = tid; i < 8 * CDIM; i += 256)
        wsh[i] = Wkv[(size_t)(CDIM + j0) * CDIM + i];
    __syncthreads();
    int w = tid >> 5, lane = tid & 31;
    const float* wr = &wsh[w * CDIM];
    float bias = bkv[CDIM + j0 + w];
    for (int b = b0; b < b0 + BATCH / BSPLIT; b++) {
        const float* yb = &g_y[((size_t)b * NHEAD + h) * CDIM];
        float s = 0.f;
        #pragma unroll
        for (int c = lane; c < CDIM; c += 32) s += yb[c] * wr[c];
        #pragma unroll
        for (int off = 16; off; off >>= 1) s += __shfl_down_sync(0xffffffffu, s, off);
        if (lane == 0) g_o[b * CDIM + j0 + w] = s + bias;
    }
}

// ---------------- K8: output projection (weight-stationary) ----------------
__global__ __launch_bounds__(256) void k_outproj(float* __restrict__ out,
                                                 const float* __restrict__ Wo,
                                                 const float* __restrict__ bo,
                                                 int out_cols, int bo_n) {
    __shared__ float wsh[8 * CDIM];
    int tid = threadIdx.x;
    int j0 = blockIdx.x * 8;
    int b0 = blockIdx.y * (BATCH / BSPLIT);
    if (j0 >= out_cols) return;
    for (int i = tid; i < 8 * CDIM; i += 256) {
        if (j0 + (i / CDIM) < out_cols) wsh[i] = Wo[(size_t)j0 * CDIM + i];
    }
    __syncthreads();
    int w = tid >> 5, lane = tid & 31;
    int j = j0 + w;
    if (j >= out_cols) return;
    const float* wr = &wsh[w * CDIM];
    float bias = (j < bo_n) ? bo[j] : 0.f;
    for (int b = b0; b < b0 + BATCH / BSPLIT; b++) {
        const float* ob = &g_o[b * CDIM];
        float s = 0.f;
        #pragma unroll
        for (int c = lane; c < CDIM; c += 32) s += ob[c] * wr[c];
        #pragma unroll
        for (int off = 16; off; off >>= 1) s += __shfl_down_sync(0xffffffffu, s, off);
        if (lane == 0) out[(size_t)b * out_cols + j] = s + bias;
    }
}

// ---------------- host ----------------
extern "C" void kernel_launch(void* const* d_in, const int* in_sizes, int n_in,
                              void* d_out, int out_size) {
    const float* x   = (const float*)d_in[0];
    const float* Wq  = (const float*)d_in[1];
    const float* bq  = (const float*)d_in[2];
    const float* Wkv = (const float*)d_in[3];
    const float* bkv = (const float*)d_in[4];
    const float* Wo  = (const float*)d_in[5];
    const float* bo  = (const float*)d_in[6];
    float* out = (float*)d_out;

    int B = in_sizes[0] / (NTOK * CDIM);
    int out_cols = out_size / B;
    int bo_n = (n_in > 6) ? in_sizes[6] : 0;

    cudaFuncSetAttribute(k_gemm_k, cudaFuncAttributeMaxDynamicSharedMemorySize, SMEM_K);

    k_convA  <<<(CDIM * CDIM + 255) / 256, 256>>>(Wkv);
    k_convB  <<<dim3(HW / 32, CDIM / 32, B), dim3(32, 8)>>>(x);
    k_qproj  <<<dim3(CDIM / 8, BSPLIT), 256>>>(x, Wq, bq);
    k_gemm_k <<<dim3(CDIM / 128, NTOT / 128), 256, SMEM_K>>>(bkv);
    k_pool   <<<dim3(B, (CDIM * RREG) / 256), 256>>>();
    k_route  <<<dim3(B), 256>>>();
    k_attn_lg<<<dim3(B, NHEAD, 4), 128>>>();
    k_attn_sm<<<dim3(B, NHEAD), 128>>>();
    k_yred   <<<dim3(B, 3, YSPLIT), 256>>>();
    k_ymerge <<<(YP_PLANE + 255) / 256, 256>>>();
    k_vproj  <<<dim3(CDIM / 8, BSPLIT), 256>>>(Wkv, bkv);
    k_outproj<<<dim3((out_cols + 7) / 8, BSPLIT), 256>>>(out, Wo, bo, out_cols, bo_n);
}